// round 5
// baseline (speedup 1.0000x reference)
#include <cuda_runtime.h>
#include <math.h>
#include <cstdint>

#define TOKENS  2048
#define HIDDEN  2048
#define INTER   5632
#define NEXPERTS 8
#define TOPK    2
#define NSLOTS  (TOKENS * TOPK)
#define BK 32

// ---------------- scratch ----------------
__device__ int   g_counts[NEXPERTS];
__device__ int   g_slots[NEXPERTS * NSLOTS];
__device__ float g_x[(size_t)TOKENS * HIDDEN];   // tf32-rounded x
__device__ float g_h[(size_t)NSLOTS * INTER];    // tf32-rounded hidden
__device__ float g_y[(size_t)NSLOTS * HIDDEN];

// ---------------- helpers ----------------
__device__ __forceinline__ uint32_t smem_u32(const void* p) {
    uint32_t a;
    asm("{ .reg .u64 t; cvta.to.shared.u64 t, %1; cvt.u32.u64 %0, t; }" : "=r"(a) : "l"(p));
    return a;
}
__device__ __forceinline__ uint32_t f2tf32(float f) {
    uint32_t r;
    asm("cvt.rna.tf32.f32 %0, %1;" : "=r"(r) : "f"(f));
    return r;
}
__device__ __forceinline__ void cp16(uint32_t dst, const void* src, int sz) {
    asm volatile("cp.async.cg.shared.global [%0], [%1], 16, %2;"
                 :: "r"(dst), "l"(src), "r"(sz) : "memory");
}
#define CP_COMMIT() asm volatile("cp.async.commit_group;" ::: "memory")
#define CP_WAIT0()  asm volatile("cp.async.wait_group 0;" ::: "memory")

__device__ __forceinline__ void ldsm4(uint32_t& r0, uint32_t& r1, uint32_t& r2, uint32_t& r3,
                                      uint32_t addr) {
    asm volatile("ldmatrix.sync.aligned.m8n8.x4.shared.b16 {%0,%1,%2,%3}, [%4];"
                 : "=r"(r0), "=r"(r1), "=r"(r2), "=r"(r3) : "r"(addr));
}
__device__ __forceinline__ void mma8(float& d0, float& d1, float& d2, float& d3,
                                     uint32_t a0, uint32_t a1, uint32_t a2, uint32_t a3,
                                     uint32_t b0, uint32_t b1) {
    asm volatile(
        "mma.sync.aligned.m16n8k8.row.col.f32.tf32.tf32.f32 "
        "{%0,%1,%2,%3},{%4,%5,%6,%7},{%8,%9},{%0,%1,%2,%3};"
        : "+f"(d0), "+f"(d1), "+f"(d2), "+f"(d3)
        : "r"(a0), "r"(a1), "r"(a2), "r"(a3), "r"(b0), "r"(b1));
}
__device__ __forceinline__ float silu(float g) { return g / (1.f + expf(-g)); }

// ---------------- small kernels ----------------
__global__ void zero_counts_kernel() {
    if (threadIdx.x < NEXPERTS) g_counts[threadIdx.x] = 0;
}
__global__ void route_kernel(const int* __restrict__ idx) {
    int s = blockIdx.x * blockDim.x + threadIdx.x;
    if (s >= NSLOTS) return;
    int e = idx[s];
    int pos = atomicAdd(&g_counts[e], 1);
    g_slots[e * NSLOTS + pos] = s;
}
__global__ void round_x_kernel(const float* __restrict__ x) {
    int i = blockIdx.x * blockDim.x + threadIdx.x;
    if (i >= TOKENS * HIDDEN / 4) return;
    float4 v = *(const float4*)(x + i * 4);
    float4 o;
    o.x = __uint_as_float(f2tf32(v.x));
    o.y = __uint_as_float(f2tf32(v.y));
    o.z = __uint_as_float(f2tf32(v.z));
    o.w = __uint_as_float(f2tf32(v.w));
    *(float4*)(g_x + i * 4) = o;
}

// ================= stage 1 =================
// CTA 128 rows x 64 cols (gate+up). 8 warps (4m x 2n), warp tile 32x32.
// smem: A0@0 A1@16384 | B1:32768+cur*8192 | B3:49152+cur*8192 | rows@65536
#define S1_SMEM 66048
extern __shared__ char smem[];

__global__ __launch_bounds__(256, 2)
void ffn1_mma(const float* __restrict__ w1, const float* __restrict__ w3) {
    const int e = blockIdx.z;
    const int count = g_counts[e];
    const int row0 = blockIdx.x * 128;
    if (row0 >= count) return;
    const int colbase = blockIdx.y * 64;

    const int tid = threadIdx.x;
    const int lane = tid & 31;
    const int wid = tid >> 5;
    const int q = lane & 3, gid = lane >> 2;
    const int warpm = wid >> 1, warpn = wid & 1;

    int* rowsS = (int*)(smem + 65536);
    if (tid < 128) {
        int r = row0 + tid;
        rowsS[tid] = (r < count) ? g_slots[e * NSLOTS + r] : -1;
    }
    __syncthreads();

    const uint32_t sb = smem_u32(smem);
    const float* w1p = w1 + (size_t)e * HIDDEN * INTER + colbase;
    const float* w3p = w3 + (size_t)e * HIDDEN * INTER + colbase;

    // ldmatrix per-lane geometry
    const int jrow  = lane & 7;
    const int jh    = (lane >> 3) & 1;   // A: +8 rows   | B: chunk hi
    const int jt    = lane >> 4;         // A: chunk hi  | B: nt odd
    // A rows for mt=0,1
    int rowA[2];
    rowA[0] = warpm * 32 + jh * 8 + jrow;
    rowA[1] = rowA[0] + 16;
    const uint32_t aoff0 = (uint32_t)rowA[0] * 128, am0 = (uint32_t)(rowA[0] & 7);
    const uint32_t aoff1 = (uint32_t)rowA[1] * 128, am1 = (uint32_t)(rowA[1] & 7);
    // B rows for pair p=0,1 (same geometry for B1 and B3)
    int rowB[2];
    rowB[0] = warpn * 32 + (2 * 0 + jt) * 8 + jrow;
    rowB[1] = warpn * 32 + (2 * 1 + jt) * 8 + jrow;
    const uint32_t boff0 = (uint32_t)rowB[0] * 128, bm0 = (uint32_t)(rowB[0] & 7);
    const uint32_t boff1 = (uint32_t)rowB[1] * 128, bm1 = (uint32_t)(rowB[1] & 7);

    float ag[2][4][4], au[2][4][4];
    #pragma unroll
    for (int i = 0; i < 2; i++)
        #pragma unroll
        for (int j = 0; j < 4; j++)
            #pragma unroll
            for (int k = 0; k < 4; k++) { ag[i][j][k] = 0.f; au[i][j][k] = 0.f; }

    float v1[2][4], v3[2][4];

    // ---- prologue: chunk 0 ----
    #pragma unroll
    for (int p = 0; p < 2; p++) {
        int t = tid + p * 256;
        int n = t & 63, kg = t >> 6;
        #pragma unroll
        for (int j = 0; j < 4; j++) {
            v1[p][j] = w1p[(size_t)(kg * 4 + j) * INTER + n];
            v3[p][j] = w3p[(size_t)(kg * 4 + j) * INTER + n];
        }
    }
    #pragma unroll
    for (int p = 0; p < 4; p++) {
        int t = tid + p * 256;
        int r = t >> 3, g = t & 7;
        int slot = rowsS[r];
        uint32_t dst = sb + r * 128 + ((g ^ (r & 7)) << 4);
        cp16(dst, g_x + (size_t)(slot >> 1) * HIDDEN + g * 4, slot >= 0 ? 16 : 0);
    }
    CP_COMMIT();
    #pragma unroll
    for (int p = 0; p < 2; p++) {
        int t = tid + p * 256;
        int n = t & 63, kg = t >> 6;
        uint32_t soff = n * 128 + ((kg ^ (n & 7)) << 4);
        uint4 o1, o3;
        o1.x = f2tf32(v1[p][0]); o1.y = f2tf32(v1[p][1]); o1.z = f2tf32(v1[p][2]); o1.w = f2tf32(v1[p][3]);
        o3.x = f2tf32(v3[p][0]); o3.y = f2tf32(v3[p][1]); o3.z = f2tf32(v3[p][2]); o3.w = f2tf32(v3[p][3]);
        *(uint4*)(smem + 32768 + soff) = o1;
        *(uint4*)(smem + 49152 + soff) = o3;
    }
    CP_WAIT0();
    __syncthreads();

    const int NCH = HIDDEN / BK;  // 64
    for (int i = 0; i < NCH; i++) {
        int cur = i & 1, nxt = cur ^ 1;
        int k0n = (i + 1) * BK;
        if (i + 1 < NCH) {
            #pragma unroll
            for (int p = 0; p < 2; p++) {
                int t = tid + p * 256;
                int n = t & 63, kg = t >> 6;
                #pragma unroll
                for (int j = 0; j < 4; j++) {
                    v1[p][j] = w1p[(size_t)(k0n + kg * 4 + j) * INTER + n];
                    v3[p][j] = w3p[(size_t)(k0n + kg * 4 + j) * INTER + n];
                }
            }
            #pragma unroll
            for (int p = 0; p < 4; p++) {
                int t = tid + p * 256;
                int r = t >> 3, g = t & 7;
                int slot = rowsS[r];
                uint32_t dst = sb + nxt * 16384 + r * 128 + ((g ^ (r & 7)) << 4);
                cp16(dst, g_x + (size_t)(slot >> 1) * HIDDEN + k0n + g * 4, slot >= 0 ? 16 : 0);
            }
            CP_COMMIT();
        }

        const uint32_t Ab  = sb + cur * 16384;
        const uint32_t B1b = sb + 32768 + cur * 8192;
        const uint32_t B3b = sb + 49152 + cur * 8192;
        #pragma unroll
        for (int ks = 0; ks < 4; ks++) {
            uint32_t cA = (uint32_t)(ks * 2 + jt);
            uint32_t cB = (uint32_t)(ks * 2 + jh);
            uint32_t a[2][4], b1[2][4], b3[2][4];
            ldsm4(a[0][0], a[0][1], a[0][2], a[0][3], Ab + aoff0 + ((cA ^ am0) << 4));
            ldsm4(a[1][0], a[1][1], a[1][2], a[1][3], Ab + aoff1 + ((cA ^ am1) << 4));
            ldsm4(b1[0][0], b1[0][1], b1[0][2], b1[0][3], B1b + boff0 + ((cB ^ bm0) << 4));
            ldsm4(b1[1][0], b1[1][1], b1[1][2], b1[1][3], B1b + boff1 + ((cB ^ bm1) << 4));
            ldsm4(b3[0][0], b3[0][1], b3[0][2], b3[0][3], B3b + boff0 + ((cB ^ bm0) << 4));
            ldsm4(b3[1][0], b3[1][1], b3[1][2], b3[1][3], B3b + boff1 + ((cB ^ bm1) << 4));
            #pragma unroll
            for (int p = 0; p < 2; p++) {
                #pragma unroll
                for (int h = 0; h < 2; h++) {
                    int nt = 2 * p + h;
                    #pragma unroll
                    for (int mt = 0; mt < 2; mt++) {
                        mma8(ag[mt][nt][0], ag[mt][nt][1], ag[mt][nt][2], ag[mt][nt][3],
                             a[mt][0], a[mt][1], a[mt][2], a[mt][3], b1[p][2 * h], b1[p][2 * h + 1]);
                        mma8(au[mt][nt][0], au[mt][nt][1], au[mt][nt][2], au[mt][nt][3],
                             a[mt][0], a[mt][1], a[mt][2], a[mt][3], b3[p][2 * h], b3[p][2 * h + 1]);
                    }
                }
            }
        }

        if (i + 1 < NCH) {
            #pragma unroll
            for (int p = 0; p < 2; p++) {
                int t = tid + p * 256;
                int n = t & 63, kg = t >> 6;
                uint32_t soff = n * 128 + ((kg ^ (n & 7)) << 4);
                uint4 o1, o3;
                o1.x = f2tf32(v1[p][0]); o1.y = f2tf32(v1[p][1]); o1.z = f2tf32(v1[p][2]); o1.w = f2tf32(v1[p][3]);
                o3.x = f2tf32(v3[p][0]); o3.y = f2tf32(v3[p][1]); o3.z = f2tf32(v3[p][2]); o3.w = f2tf32(v3[p][3]);
                *(uint4*)(smem + 32768 + nxt * 8192 + soff) = o1;
                *(uint4*)(smem + 49152 + nxt * 8192 + soff) = o3;
            }
        }
        CP_WAIT0();
        __syncthreads();
    }

    // ---- epilogue ----
    #pragma unroll
    for (int mt = 0; mt < 2; mt++) {
        #pragma unroll
        for (int half = 0; half < 2; half++) {
            int r = warpm * 32 + mt * 16 + gid + half * 8;
            int slot = rowsS[r];
            if (slot < 0) continue;
            float* dst = g_h + (size_t)slot * INTER + colbase + warpn * 32;
            #pragma unroll
            for (int nt = 0; nt < 4; nt++) {
                float gg0 = ag[mt][nt][half * 2 + 0], uu0 = au[mt][nt][half * 2 + 0];
                float gg1 = ag[mt][nt][half * 2 + 1], uu1 = au[mt][nt][half * 2 + 1];
                float2 o;
                o.x = __uint_as_float(f2tf32(silu(gg0) * uu0));
                o.y = __uint_as_float(f2tf32(silu(gg1) * uu1));
                *(float2*)(dst + nt * 8 + 2 * q) = o;
            }
        }
    }
}

// ================= stage 2 =================
// CTA 128x128. 8 warps (4m x 2n), warp tile 32x64.
// smem: A0@0 A1@16384 | B0@32768 B1@49152 | rows@65536
#define S2_SMEM 66048

__global__ __launch_bounds__(256, 2)
void ffn2_mma(const float* __restrict__ w2) {
    const int e = blockIdx.z;
    const int count = g_counts[e];
    const int row0 = blockIdx.x * 128;
    if (row0 >= count) return;
    const int colbase = blockIdx.y * 128;

    const int tid = threadIdx.x;
    const int lane = tid & 31;
    const int wid = tid >> 5;
    const int q = lane & 3, gid = lane >> 2;
    const int warpm = wid >> 1, warpn = wid & 1;

    int* rowsS = (int*)(smem + 65536);
    if (tid < 128) {
        int r = row0 + tid;
        rowsS[tid] = (r < count) ? g_slots[e * NSLOTS + r] : -1;
    }
    __syncthreads();

    const uint32_t sb = smem_u32(smem);
    const float* w2p = w2 + (size_t)e * INTER * HIDDEN + colbase;

    const int jrow = lane & 7;
    const int jh   = (lane >> 3) & 1;
    const int jt   = lane >> 4;
    int rowA[2];
    rowA[0] = warpm * 32 + jh * 8 + jrow;
    rowA[1] = rowA[0] + 16;
    const uint32_t aoff0 = (uint32_t)rowA[0] * 128, am0 = (uint32_t)(rowA[0] & 7);
    const uint32_t aoff1 = (uint32_t)rowA[1] * 128, am1 = (uint32_t)(rowA[1] & 7);
    uint32_t boff[4], bm[4];
    #pragma unroll
    for (int p = 0; p < 4; p++) {
        int nr = warpn * 64 + (2 * p + jt) * 8 + jrow;
        boff[p] = (uint32_t)nr * 128;
        bm[p] = (uint32_t)(nr & 7);
    }

    float acc[2][8][4];
    #pragma unroll
    for (int i = 0; i < 2; i++)
        #pragma unroll
        for (int j = 0; j < 8; j++)
            #pragma unroll
            for (int k = 0; k < 4; k++) acc[i][j][k] = 0.f;

    float vb[4][4];

    #pragma unroll
    for (int p = 0; p < 4; p++) {
        int t = tid + p * 256;
        int n = t & 127, kg = t >> 7;
        #pragma unroll
        for (int j = 0; j < 4; j++)
            vb[p][j] = w2p[(size_t)(kg * 4 + j) * HIDDEN + n];
    }
    #pragma unroll
    for (int p = 0; p < 4; p++) {
        int t = tid + p * 256;
        int r = t >> 3, g = t & 7;
        int slot = rowsS[r];
        uint32_t dst = sb + r * 128 + ((g ^ (r & 7)) << 4);
        cp16(dst, g_h + (size_t)slot * INTER + g * 4, slot >= 0 ? 16 : 0);
    }
    CP_COMMIT();
    #pragma unroll
    for (int p = 0; p < 4; p++) {
        int t = tid + p * 256;
        int n = t & 127, kg = t >> 7;
        uint32_t soff = n * 128 + ((kg ^ (n & 7)) << 4);
        uint4 o;
        o.x = f2tf32(vb[p][0]); o.y = f2tf32(vb[p][1]); o.z = f2tf32(vb[p][2]); o.w = f2tf32(vb[p][3]);
        *(uint4*)(smem + 32768 + soff) = o;
    }
    CP_WAIT0();
    __syncthreads();

    const int NCH = INTER / BK;  // 176
    for (int i = 0; i < NCH; i++) {
        int cur = i & 1, nxt = cur ^ 1;
        int k0n = (i + 1) * BK;
        if (i + 1 < NCH) {
            #pragma unroll
            for (int p = 0; p < 4; p++) {
                int t = tid + p * 256;
                int n = t & 127, kg = t >> 7;
                #pragma unroll
                for (int j = 0; j < 4; j++)
                    vb[p][j] = w2p[(size_t)(k0n + kg * 4 + j) * HIDDEN + n];
            }
            #pragma unroll
            for (int p = 0; p < 4; p++) {
                int t = tid + p * 256;
                int r = t >> 3, g = t & 7;
                int slot = rowsS[r];
                uint32_t dst = sb + nxt * 16384 + r * 128 + ((g ^ (r & 7)) << 4);
                cp16(dst, g_h + (size_t)slot * INTER + k0n + g * 4, slot >= 0 ? 16 : 0);
            }
            CP_COMMIT();
        }

        const uint32_t Ab = sb + cur * 16384;
        const uint32_t Bb = sb + 32768 + cur * 16384;
        #pragma unroll
        for (int ks = 0; ks < 4; ks++) {
            uint32_t cA = (uint32_t)(ks * 2 + jt);
            uint32_t cB = (uint32_t)(ks * 2 + jh);
            uint32_t a[2][4], b[4][4];
            ldsm4(a[0][0], a[0][1], a[0][2], a[0][3], Ab + aoff0 + ((cA ^ am0) << 4));
            ldsm4(a[1][0], a[1][1], a[1][2], a[1][3], Ab + aoff1 + ((cA ^ am1) << 4));
            #pragma unroll
            for (int p = 0; p < 4; p++)
                ldsm4(b[p][0], b[p][1], b[p][2], b[p][3], Bb + boff[p] + ((cB ^ bm[p]) << 4));
            #pragma unroll
            for (int p = 0; p < 4; p++) {
                #pragma unroll
                for (int h = 0; h < 2; h++) {
                    int nt = 2 * p + h;
                    #pragma unroll
                    for (int mt = 0; mt < 2; mt++)
                        mma8(acc[mt][nt][0], acc[mt][nt][1], acc[mt][nt][2], acc[mt][nt][3],
                             a[mt][0], a[mt][1], a[mt][2], a[mt][3], b[p][2 * h], b[p][2 * h + 1]);
                }
            }
        }

        if (i + 1 < NCH) {
            #pragma unroll
            for (int p = 0; p < 4; p++) {
                int t = tid + p * 256;
                int n = t & 127, kg = t >> 7;
                uint32_t soff = n * 128 + ((kg ^ (n & 7)) << 4);
                uint4 o;
                o.x = f2tf32(vb[p][0]); o.y = f2tf32(vb[p][1]); o.z = f2tf32(vb[p][2]); o.w = f2tf32(vb[p][3]);
                *(uint4*)(smem + 32768 + nxt * 16384 + soff) = o;
            }
        }
        CP_WAIT0();
        __syncthreads();
    }

    #pragma unroll
    for (int mt = 0; mt < 2; mt++) {
        #pragma unroll
        for (int half = 0; half < 2; half++) {
            int r = warpm * 32 + mt * 16 + gid + half * 8;
            int slot = rowsS[r];
            if (slot < 0) continue;
            float* dst = g_y + (size_t)slot * HIDDEN + colbase + warpn * 64;
            #pragma unroll
            for (int nt = 0; nt < 8; nt++) {
                float2 o;
                o.x = acc[mt][nt][half * 2 + 0];
                o.y = acc[mt][nt][half * 2 + 1];
                *(float2*)(dst + nt * 8 + 2 * q) = o;
            }
        }
    }
}

// ---------------- combine ----------------
__global__ void combine_kernel(const float* __restrict__ ew,
                               float* __restrict__ out) {
    int i = blockIdx.x * blockDim.x + threadIdx.x;
    const int n4 = TOKENS * HIDDEN / 4;
    if (i >= n4) return;
    int t  = i / (HIDDEN / 4);
    int c4 = (i % (HIDDEN / 4)) * 4;
    float w0 = ew[t * 2 + 0];
    float w1v = ew[t * 2 + 1];
    float4 y0 = *(const float4*)(g_y + (size_t)(2 * t + 0) * HIDDEN + c4);
    float4 y1 = *(const float4*)(g_y + (size_t)(2 * t + 1) * HIDDEN + c4);
    float4 o;
    o.x = w0 * y0.x + w1v * y1.x;
    o.y = w0 * y0.y + w1v * y1.y;
    o.z = w0 * y0.z + w1v * y1.z;
    o.w = w0 * y0.w + w1v * y1.w;
    *(float4*)(out + (size_t)t * HIDDEN + c4) = o;
}

// ---------------- launch ----------------
extern "C" void kernel_launch(void* const* d_in, const int* in_sizes, int n_in,
                              void* d_out, int out_size) {
    const float* x   = (const float*)d_in[0];
    const float* ew  = (const float*)d_in[1];
    const float* w1  = (const float*)d_in[2];
    const float* w2  = (const float*)d_in[3];
    const float* w3  = (const float*)d_in[4];
    const int*   idx = (const int*)d_in[5];
    float* out = (float*)d_out;

    cudaFuncSetAttribute(ffn1_mma, cudaFuncAttributeMaxDynamicSharedMemorySize, S1_SMEM);
    cudaFuncSetAttribute(ffn2_mma, cudaFuncAttributeMaxDynamicSharedMemorySize, S2_SMEM);

    zero_counts_kernel<<<1, 32>>>();
    route_kernel<<<NSLOTS / 256, 256>>>(idx);
    round_x_kernel<<<(TOKENS * HIDDEN / 4 + 255) / 256, 256>>>(x);

    dim3 g1(NSLOTS / 128, INTER / 64, NEXPERTS);    // mtile fastest
    ffn1_mma<<<g1, 256, S1_SMEM>>>(w1, w3);

    dim3 g2(NSLOTS / 128, HIDDEN / 128, NEXPERTS);
    ffn2_mma<<<g2, 256, S2_SMEM>>>(w2);

    combine_kernel<<<(TOKENS * HIDDEN / 4 + 255) / 256, 256>>>(ew, out);
}

// round 6
// speedup vs baseline: 1.0213x; 1.0213x over previous
#include <cuda_runtime.h>
#include <math.h>
#include <cstdint>

#define TOKENS  2048
#define HIDDEN  2048
#define INTER   5632
#define NEXPERTS 8
#define TOPK    2
#define NSLOTS  (TOKENS * TOPK)
#define BK 32

// ---------------- scratch ----------------
__device__ int   g_counts[NEXPERTS];
__device__ int   g_slots[NEXPERTS * NSLOTS];
__device__ float g_x[(size_t)TOKENS * HIDDEN];     // tf32-rounded x
__device__ float g_gate[(size_t)NSLOTS * INTER];   // raw f32 gate
__device__ float g_h[(size_t)NSLOTS * INTER];      // tf32-rounded silu(g)*u
__device__ float g_y[(size_t)NSLOTS * HIDDEN];

// ---------------- helpers ----------------
__device__ __forceinline__ uint32_t smem_u32(const void* p) {
    uint32_t a;
    asm("{ .reg .u64 t; cvta.to.shared.u64 t, %1; cvt.u32.u64 %0, t; }" : "=r"(a) : "l"(p));
    return a;
}
__device__ __forceinline__ uint32_t f2tf32(float f) {
    uint32_t r;
    asm("cvt.rna.tf32.f32 %0, %1;" : "=r"(r) : "f"(f));
    return r;
}
__device__ __forceinline__ void cp16(uint32_t dst, const void* src, int sz) {
    asm volatile("cp.async.cg.shared.global [%0], [%1], 16, %2;"
                 :: "r"(dst), "l"(src), "r"(sz) : "memory");
}
#define CP_COMMIT() asm volatile("cp.async.commit_group;" ::: "memory")
#define CP_WAIT0()  asm volatile("cp.async.wait_group 0;" ::: "memory")

__device__ __forceinline__ void ldsm4(uint32_t* r, uint32_t addr) {
    asm volatile("ldmatrix.sync.aligned.m8n8.x4.shared.b16 {%0,%1,%2,%3}, [%4];"
                 : "=r"(r[0]), "=r"(r[1]), "=r"(r[2]), "=r"(r[3]) : "r"(addr));
}
__device__ __forceinline__ void mma8(float* d,
                                     const uint32_t* a, uint32_t b0, uint32_t b1) {
    asm volatile(
        "mma.sync.aligned.m16n8k8.row.col.f32.tf32.tf32.f32 "
        "{%0,%1,%2,%3},{%4,%5,%6,%7},{%8,%9},{%0,%1,%2,%3};"
        : "+f"(d[0]), "+f"(d[1]), "+f"(d[2]), "+f"(d[3])
        : "r"(a[0]), "r"(a[1]), "r"(a[2]), "r"(a[3]), "r"(b0), "r"(b1));
}
__device__ __forceinline__ float silu(float g) { return g / (1.f + expf(-g)); }

// ---------------- small kernels ----------------
__global__ void zero_counts_kernel() {
    if (threadIdx.x < NEXPERTS) g_counts[threadIdx.x] = 0;
}
__global__ void route_kernel(const int* __restrict__ idx) {
    int s = blockIdx.x * blockDim.x + threadIdx.x;
    if (s >= NSLOTS) return;
    int e = idx[s];
    int pos = atomicAdd(&g_counts[e], 1);
    g_slots[e * NSLOTS + pos] = s;
}
__global__ void round_x_kernel(const float* __restrict__ x) {
    int i = blockIdx.x * blockDim.x + threadIdx.x;
    if (i >= TOKENS * HIDDEN / 4) return;
    float4 v = *(const float4*)(x + i * 4);
    float4 o;
    o.x = __uint_as_float(f2tf32(v.x));
    o.y = __uint_as_float(f2tf32(v.y));
    o.z = __uint_as_float(f2tf32(v.z));
    o.w = __uint_as_float(f2tf32(v.w));
    *(float4*)(g_x + i * 4) = o;
}

// ================= unified grouped GEMM =================
// CTA 128 rows x 128 cols, BK=32. 8 warps as (2 warpm x 4 warpn), warp tile 64x32.
// smem: A[2]@0 (16KB each) | Bldm[2]@32768 (16KB each) | rows@65536
// EPI: 0 = raw f32 store; 1 = read Gate, h = tf32(silu(gate)*acc)
#define G_SMEM 66048
extern __shared__ char smem[];

template<int KD, int ND, int SH, int EPI>
__global__ __launch_bounds__(256, 2)
void gemm_tc(const float* __restrict__ Abase,
             const float* __restrict__ Wbase,
             const float* __restrict__ Gate,
             float* __restrict__ Out) {
    const int e = blockIdx.z;
    const int count = g_counts[e];
    const int row0 = blockIdx.x * 128;
    if (row0 >= count) return;
    const int colbase = blockIdx.y * 128;

    const int tid  = threadIdx.x;
    const int lane = tid & 31;
    const int wid  = tid >> 5;
    const int q = lane & 3, gid = lane >> 2;
    const int warpm = wid >> 2;        // 0..1
    const int warpn = wid & 3;         // 0..3

    int* rowsS = (int*)(smem + 65536);
    if (tid < 128) {
        int r = row0 + tid;
        rowsS[tid] = (r < count) ? g_slots[e * NSLOTS + r] : -1;
    }
    __syncthreads();

    const uint32_t sb = smem_u32(smem);
    const float* Wp = Wbase + (size_t)e * KD * ND + colbase;

    // ---- ldmatrix address precompute (XOR-folded) ----
    // A: per mt (4), rows warpm*64 + mt*16
    uint32_t BRA[4], MHA[4];
    {
        int cl = lane >> 4;                      // k-half select
        #pragma unroll
        for (int mt = 0; mt < 4; mt++) {
            int row = warpm * 64 + mt * 16 + ((lane >> 3) & 1) * 8 + (lane & 7);
            int m3 = row & 7;
            BRA[mt] = (uint32_t)(row * 128 + ((cl ^ (m3 & 1)) << 4));
            MHA[mt] = (uint32_t)(m3 >> 1);
        }
    }
    // B: per u (2), rows warpn*32 + (2u + (lane>>4))*8
    uint32_t BRB[2], MHB[2];
    {
        int cB = (lane >> 3) & 1;
        #pragma unroll
        for (int u = 0; u < 2; u++) {
            int row = warpn * 32 + (2 * u + (lane >> 4)) * 8 + (lane & 7);
            int m3 = row & 7;
            BRB[u] = (uint32_t)(row * 128 + ((cB ^ (m3 & 1)) << 4));
            MHB[u] = (uint32_t)(m3 >> 1);
        }
    }

    // ---- loader task precompute ----
    int aslot[4];
    uint32_t dstA[4];
    const float* pA[4];
    #pragma unroll
    for (int p = 0; p < 4; p++) {
        int t = tid + p * 256;
        int ar = t >> 3, ag = t & 7;
        aslot[p] = rowsS[ar];
        dstA[p] = (uint32_t)(ar * 128 + ((ag ^ (ar & 7)) << 4));
        int arow = (aslot[p] >= 0) ? (aslot[p] >> SH) : 0;
        pA[p] = Abase + (size_t)arow * KD + ag * 4;
    }
    const float* pB[4];
    uint32_t stsB[4];
    #pragma unroll
    for (int p = 0; p < 4; p++) {
        int t = tid + p * 256;
        int bn = t & 127, bkg = t >> 7;
        pB[p] = Wp + (size_t)(bkg * 4) * ND + bn;
        stsB[p] = (uint32_t)(bn * 128 + ((bkg ^ (bn & 7)) << 4));
    }

    float acc[4][4][4];
    #pragma unroll
    for (int i = 0; i < 4; i++)
        #pragma unroll
        for (int j = 0; j < 4; j++)
            #pragma unroll
            for (int k = 0; k < 4; k++) acc[i][j][k] = 0.f;

    float vb[4][4];

    // ---- prologue: chunk 0 ----
    #pragma unroll
    for (int p = 0; p < 4; p++) {
        #pragma unroll
        for (int j = 0; j < 4; j++) vb[p][j] = pB[p][(size_t)j * ND];
        pB[p] += (size_t)BK * ND;
    }
    #pragma unroll
    for (int p = 0; p < 4; p++) {
        cp16(sb + dstA[p], pA[p], aslot[p] >= 0 ? 16 : 0);
        pA[p] += BK;
    }
    CP_COMMIT();
    #pragma unroll
    for (int p = 0; p < 4; p++) {
        uint4 o;
        o.x = f2tf32(vb[p][0]); o.y = f2tf32(vb[p][1]);
        o.z = f2tf32(vb[p][2]); o.w = f2tf32(vb[p][3]);
        *(uint4*)(smem + 32768 + stsB[p]) = o;
    }
    CP_WAIT0();
    __syncthreads();

    const int NCH = KD / BK;
    for (int i = 0; i < NCH; i++) {
        const int cur = i & 1, nxt = cur ^ 1;
        if (i + 1 < NCH) {
            #pragma unroll
            for (int p = 0; p < 4; p++) {
                #pragma unroll
                for (int j = 0; j < 4; j++) vb[p][j] = pB[p][(size_t)j * ND];
                pB[p] += (size_t)BK * ND;
            }
            #pragma unroll
            for (int p = 0; p < 4; p++) {
                cp16(sb + nxt * 16384 + dstA[p], pA[p], aslot[p] >= 0 ? 16 : 0);
                pA[p] += BK;
            }
            CP_COMMIT();
        }

        // ---- mma burst ----
        const uint32_t bufA = sb + cur * 16384;
        const uint32_t bufB = sb + 32768 + cur * 16384;
        #pragma unroll
        for (int ks = 0; ks < 4; ks++) {
            uint32_t a[4][4], b[2][4];
            #pragma unroll
            for (int mt = 0; mt < 4; mt++)
                ldsm4(a[mt], bufA + BRA[mt] + (((uint32_t)ks ^ MHA[mt]) << 5));
            #pragma unroll
            for (int u = 0; u < 2; u++)
                ldsm4(b[u], bufB + BRB[u] + (((uint32_t)ks ^ MHB[u]) << 5));
            #pragma unroll
            for (int mt = 0; mt < 4; mt++) {
                #pragma unroll
                for (int nt = 0; nt < 4; nt++)
                    mma8(acc[mt][nt], a[mt], b[nt >> 1][2 * (nt & 1)], b[nt >> 1][2 * (nt & 1) + 1]);
            }
        }

        if (i + 1 < NCH) {
            #pragma unroll
            for (int p = 0; p < 4; p++) {
                uint4 o;
                o.x = f2tf32(vb[p][0]); o.y = f2tf32(vb[p][1]);
                o.z = f2tf32(vb[p][2]); o.w = f2tf32(vb[p][3]);
                *(uint4*)(smem + 32768 + nxt * 16384 + stsB[p]) = o;
            }
        }
        CP_WAIT0();
        __syncthreads();
    }

    // ---- epilogue ----
    #pragma unroll
    for (int mt = 0; mt < 4; mt++) {
        #pragma unroll
        for (int half = 0; half < 2; half++) {
            int row = warpm * 64 + mt * 16 + gid + half * 8;
            int slot = rowsS[row];
            if (slot < 0) continue;
            size_t obase = (size_t)slot * ND + colbase + warpn * 32 + 2 * q;
            #pragma unroll
            for (int nt = 0; nt < 4; nt++) {
                float c0 = acc[mt][nt][half * 2 + 0];
                float c1 = acc[mt][nt][half * 2 + 1];
                if (EPI == 1) {
                    float2 gv = *(const float2*)(Gate + obase + nt * 8);
                    float2 o;
                    o.x = __uint_as_float(f2tf32(silu(gv.x) * c0));
                    o.y = __uint_as_float(f2tf32(silu(gv.y) * c1));
                    *(float2*)(Out + obase + nt * 8) = o;
                } else {
                    float2 o; o.x = c0; o.y = c1;
                    *(float2*)(Out + obase + nt * 8) = o;
                }
            }
        }
    }
}

// ---------------- combine ----------------
__global__ void combine_kernel(const float* __restrict__ ew,
                               float* __restrict__ out) {
    int i = blockIdx.x * blockDim.x + threadIdx.x;
    const int n4 = TOKENS * HIDDEN / 4;
    if (i >= n4) return;
    int t  = i / (HIDDEN / 4);
    int c4 = (i % (HIDDEN / 4)) * 4;
    float w0 = ew[t * 2 + 0];
    float w1v = ew[t * 2 + 1];
    float4 y0 = *(const float4*)(g_y + (size_t)(2 * t + 0) * HIDDEN + c4);
    float4 y1 = *(const float4*)(g_y + (size_t)(2 * t + 1) * HIDDEN + c4);
    float4 o;
    o.x = w0 * y0.x + w1v * y1.x;
    o.y = w0 * y0.y + w1v * y1.y;
    o.z = w0 * y0.z + w1v * y1.z;
    o.w = w0 * y0.w + w1v * y1.w;
    *(float4*)(out + (size_t)t * HIDDEN + c4) = o;
}

// ---------------- launch ----------------
extern "C" void kernel_launch(void* const* d_in, const int* in_sizes, int n_in,
                              void* d_out, int out_size) {
    const float* x   = (const float*)d_in[0];
    const float* ew  = (const float*)d_in[1];
    const float* w1  = (const float*)d_in[2];
    const float* w2  = (const float*)d_in[3];
    const float* w3  = (const float*)d_in[4];
    const int*   idx = (const int*)d_in[5];
    float* out = (float*)d_out;

    float* gx = nullptr; float* gg = nullptr; float* gh = nullptr; float* gy = nullptr;
    cudaGetSymbolAddress((void**)&gx, g_x);
    cudaGetSymbolAddress((void**)&gg, g_gate);
    cudaGetSymbolAddress((void**)&gh, g_h);
    cudaGetSymbolAddress((void**)&gy, g_y);

    auto kGate = gemm_tc<HIDDEN, INTER, 1, 0>;
    auto kUp   = gemm_tc<HIDDEN, INTER, 1, 1>;
    auto kDown = gemm_tc<INTER, HIDDEN, 0, 0>;
    cudaFuncSetAttribute(kGate, cudaFuncAttributeMaxDynamicSharedMemorySize, G_SMEM);
    cudaFuncSetAttribute(kUp,   cudaFuncAttributeMaxDynamicSharedMemorySize, G_SMEM);
    cudaFuncSetAttribute(kDown, cudaFuncAttributeMaxDynamicSharedMemorySize, G_SMEM);

    zero_counts_kernel<<<1, 32>>>();
    route_kernel<<<NSLOTS / 256, 256>>>(idx);
    round_x_kernel<<<(TOKENS * HIDDEN / 4 + 255) / 256, 256>>>(x);

    dim3 g1(NSLOTS / 128, INTER / 128, NEXPERTS);   // Mtile fastest for L2 reuse
    kGate<<<g1, 256, G_SMEM>>>(gx, w1, nullptr, gg);
    kUp  <<<g1, 256, G_SMEM>>>(gx, w3, gg, gh);

    dim3 g2(NSLOTS / 128, HIDDEN / 128, NEXPERTS);
    kDown<<<g2, 256, G_SMEM>>>(gh, w2, nullptr, gy);

    combine_kernel<<<(TOKENS * HIDDEN / 4 + 255) / 256, 256>>>(ew, out);
}

// round 7
// speedup vs baseline: 1.0742x; 1.0518x over previous
#include <cuda_runtime.h>
#include <math.h>
#include <cstdint>

#define TOKENS  2048
#define HIDDEN  2048
#define INTER   5632
#define NEXPERTS 8
#define TOPK    2
#define NSLOTS  (TOKENS * TOPK)
#define BK 32

// ---------------- scratch ----------------
__device__ int   g_counts[NEXPERTS];
__device__ int   g_slots[NEXPERTS * NSLOTS];
__device__ float g_x[(size_t)TOKENS * HIDDEN];     // tf32-rounded x
__device__ float g_gate[(size_t)NSLOTS * INTER];   // raw f32 gate
__device__ float g_h[(size_t)NSLOTS * INTER];      // tf32-rounded silu(g)*u
__device__ float g_y[(size_t)NSLOTS * HIDDEN];

// ---------------- helpers ----------------
__device__ __forceinline__ uint32_t smem_u32(const void* p) {
    uint32_t a;
    asm("{ .reg .u64 t; cvta.to.shared.u64 t, %1; cvt.u32.u64 %0, t; }" : "=r"(a) : "l"(p));
    return a;
}
__device__ __forceinline__ uint32_t f2tf32(float f) {
    uint32_t r;
    asm("cvt.rna.tf32.f32 %0, %1;" : "=r"(r) : "f"(f));
    return r;
}
__device__ __forceinline__ void cp16(uint32_t dst, const void* src, int sz) {
    asm volatile("cp.async.cg.shared.global [%0], [%1], 16, %2;"
                 :: "r"(dst), "l"(src), "r"(sz) : "memory");
}
#define CP_COMMIT() asm volatile("cp.async.commit_group;" ::: "memory")
#define CP_WAIT0()  asm volatile("cp.async.wait_group 0;" ::: "memory")

__device__ __forceinline__ void ldsm4(uint32_t* r, uint32_t addr) {
    asm volatile("ldmatrix.sync.aligned.m8n8.x4.shared.b16 {%0,%1,%2,%3}, [%4];"
                 : "=r"(r[0]), "=r"(r[1]), "=r"(r[2]), "=r"(r[3]) : "r"(addr));
}
__device__ __forceinline__ void mma8(float* d,
                                     const uint32_t* a, uint32_t b0, uint32_t b1) {
    asm volatile(
        "mma.sync.aligned.m16n8k8.row.col.f32.tf32.tf32.f32 "
        "{%0,%1,%2,%3},{%4,%5,%6,%7},{%8,%9},{%0,%1,%2,%3};"
        : "+f"(d[0]), "+f"(d[1]), "+f"(d[2]), "+f"(d[3])
        : "r"(a[0]), "r"(a[1]), "r"(a[2]), "r"(a[3]), "r"(b0), "r"(b1));
}
__device__ __forceinline__ float silu(float g) { return g / (1.f + expf(-g)); }

// ---------------- small kernels ----------------
__global__ void zero_counts_kernel() {
    if (threadIdx.x < NEXPERTS) g_counts[threadIdx.x] = 0;
}
__global__ void route_kernel(const int* __restrict__ idx) {
    int s = blockIdx.x * blockDim.x + threadIdx.x;
    if (s >= NSLOTS) return;
    int e = idx[s];
    int pos = atomicAdd(&g_counts[e], 1);
    g_slots[e * NSLOTS + pos] = s;
}
__global__ void round_x_kernel(const float* __restrict__ x) {
    int i = blockIdx.x * blockDim.x + threadIdx.x;
    if (i >= TOKENS * HIDDEN / 4) return;
    float4 v = *(const float4*)(x + i * 4);
    float4 o;
    o.x = __uint_as_float(f2tf32(v.x));
    o.y = __uint_as_float(f2tf32(v.y));
    o.z = __uint_as_float(f2tf32(v.z));
    o.w = __uint_as_float(f2tf32(v.w));
    *(float4*)(g_x + i * 4) = o;
}

// ================= unified grouped GEMM =================
// CTA 128x128, BK=32. 4 warps (2 warpm x 2 warpn), warp tile 64x64. 128 threads.
// smem: A[2]@0 (16KB) | B[2]@32768 (16KB) | rows@65536
// EPI: 0 = raw f32 store; 1 = h = tf32(silu(gate)*acc)
#define G_SMEM 66048
extern __shared__ char smem[];

template<int KD, int ND, int SH, int EPI>
__global__ __launch_bounds__(128, 2)
void gemm_tc(const float* __restrict__ Abase,
             const float* __restrict__ Wbase,
             const float* __restrict__ Gate,
             float* __restrict__ Out) {
    const int e = blockIdx.z;
    const int count = g_counts[e];
    const int row0 = blockIdx.x * 128;
    if (row0 >= count) return;
    const int colbase = blockIdx.y * 128;

    const int tid  = threadIdx.x;
    const int lane = tid & 31;
    const int wid  = tid >> 5;
    const int q = lane & 3, gid = lane >> 2;
    const int warpm = wid >> 1;        // 0..1
    const int warpn = wid & 1;         // 0..1

    int* rowsS = (int*)(smem + 65536);
    if (tid < 128) {
        int r = row0 + tid;
        rowsS[tid] = (r < count) ? g_slots[e * NSLOTS + r] : -1;
    }
    __syncthreads();

    const uint32_t sb = smem_u32(smem);
    const float* Wp = Wbase + (size_t)e * KD * ND + colbase;

    // ---- ldmatrix address precompute (XOR-folded) ----
    uint32_t BRA[4], MHA[4];
    {
        int cl = lane >> 4;                      // k-half select for A
        #pragma unroll
        for (int mt = 0; mt < 4; mt++) {
            int row = warpm * 64 + mt * 16 + ((lane >> 3) & 1) * 8 + (lane & 7);
            int m3 = row & 7;
            BRA[mt] = (uint32_t)(row * 128 + ((cl ^ (m3 & 1)) << 4));
            MHA[mt] = (uint32_t)(m3 >> 1);
        }
    }
    uint32_t BRB[4], MHB[4];
    {
        int cB = (lane >> 3) & 1;                // k-half select for B
        int jt = lane >> 4;
        #pragma unroll
        for (int u = 0; u < 4; u++) {
            int row = warpn * 64 + (2 * u + jt) * 8 + (lane & 7);
            int m3 = row & 7;
            BRB[u] = (uint32_t)(row * 128 + ((cB ^ (m3 & 1)) << 4));
            MHB[u] = (uint32_t)(m3 >> 1);
        }
    }

    // ---- loader geometry (affine in p, tid<128) ----
    // A: task p -> row ar0 + 16p, kgroup ag (fixed);  B: row tid, kgroup p.
    const int ar0 = tid >> 3;
    const int ag  = tid & 7;
    const uint32_t dstA0 = (uint32_t)(ar0 * 128 + ((ag ^ (ar0 & 7)) << 4));
    int aslot[8];
    #pragma unroll
    for (int p = 0; p < 8; p++) aslot[p] = rowsS[ar0 + p * 16];
    const uint32_t stsB0 = (uint32_t)(tid * 128);
    const int bm3 = tid & 7;

    float acc[4][8][4];
    #pragma unroll
    for (int i = 0; i < 4; i++)
        #pragma unroll
        for (int j = 0; j < 8; j++)
            #pragma unroll
            for (int k = 0; k < 4; k++) acc[i][j][k] = 0.f;

    float vb[8][4];

    // ---- prologue: chunk 0 ----
    #pragma unroll
    for (int p = 0; p < 8; p++) {
        const float* bp = Wp + (size_t)(p * 4) * ND + tid;
        #pragma unroll
        for (int j = 0; j < 4; j++) vb[p][j] = bp[(size_t)j * ND];
    }
    #pragma unroll
    for (int p = 0; p < 8; p++) {
        int arow = (aslot[p] >= 0) ? (aslot[p] >> SH) : 0;
        cp16(sb + dstA0 + p * 2048,
             Abase + (size_t)arow * KD + ag * 4,
             aslot[p] >= 0 ? 16 : 0);
    }
    CP_COMMIT();
    #pragma unroll
    for (int p = 0; p < 8; p++) {
        uint4 o;
        o.x = f2tf32(vb[p][0]); o.y = f2tf32(vb[p][1]);
        o.z = f2tf32(vb[p][2]); o.w = f2tf32(vb[p][3]);
        *(uint4*)(smem + 32768 + stsB0 + ((p ^ bm3) << 4)) = o;
    }
    CP_WAIT0();
    __syncthreads();

    const int NCH = KD / BK;
    for (int i = 0; i < NCH; i++) {
        const int cur = i & 1, nxt = cur ^ 1;
        const int k0n = (i + 1) * BK;
        if (i + 1 < NCH) {
            const float* Wn = Wp + (size_t)k0n * ND;
            #pragma unroll
            for (int p = 0; p < 8; p++) {
                const float* bp = Wn + (size_t)(p * 4) * ND + tid;
                #pragma unroll
                for (int j = 0; j < 4; j++) vb[p][j] = bp[(size_t)j * ND];
            }
            #pragma unroll
            for (int p = 0; p < 8; p++) {
                int arow = (aslot[p] >= 0) ? (aslot[p] >> SH) : 0;
                cp16(sb + nxt * 16384 + dstA0 + p * 2048,
                     Abase + (size_t)arow * KD + k0n + ag * 4,
                     aslot[p] >= 0 ? 16 : 0);
            }
            CP_COMMIT();
        }

        // ---- mma burst: warp tile 64x64 ----
        const uint32_t bufA = sb + cur * 16384;
        const uint32_t bufB = sb + 32768 + cur * 16384;
        #pragma unroll
        for (int ks = 0; ks < 4; ks++) {
            uint32_t a[4][4], b[4][4];
            #pragma unroll
            for (int mt = 0; mt < 4; mt++)
                ldsm4(a[mt], bufA + BRA[mt] + (((uint32_t)ks ^ MHA[mt]) << 5));
            #pragma unroll
            for (int u = 0; u < 4; u++)
                ldsm4(b[u], bufB + BRB[u] + (((uint32_t)ks ^ MHB[u]) << 5));
            #pragma unroll
            for (int mt = 0; mt < 4; mt++) {
                #pragma unroll
                for (int nt = 0; nt < 8; nt++)
                    mma8(acc[mt][nt], a[mt],
                         b[nt >> 1][2 * (nt & 1)], b[nt >> 1][2 * (nt & 1) + 1]);
            }
        }

        if (i + 1 < NCH) {
            #pragma unroll
            for (int p = 0; p < 8; p++) {
                uint4 o;
                o.x = f2tf32(vb[p][0]); o.y = f2tf32(vb[p][1]);
                o.z = f2tf32(vb[p][2]); o.w = f2tf32(vb[p][3]);
                *(uint4*)(smem + 32768 + nxt * 16384 + stsB0 + ((p ^ bm3) << 4)) = o;
            }
        }
        CP_WAIT0();
        __syncthreads();
    }

    // ---- epilogue ----
    #pragma unroll
    for (int mt = 0; mt < 4; mt++) {
        #pragma unroll
        for (int half = 0; half < 2; half++) {
            int row = warpm * 64 + mt * 16 + gid + half * 8;
            int slot = rowsS[row];
            if (slot < 0) continue;
            size_t obase = (size_t)slot * ND + colbase + warpn * 64 + 2 * q;
            #pragma unroll
            for (int nt = 0; nt < 8; nt++) {
                float c0 = acc[mt][nt][half * 2 + 0];
                float c1 = acc[mt][nt][half * 2 + 1];
                if (EPI == 1) {
                    float2 gv = *(const float2*)(Gate + obase + nt * 8);
                    float2 o;
                    o.x = __uint_as_float(f2tf32(silu(gv.x) * c0));
                    o.y = __uint_as_float(f2tf32(silu(gv.y) * c1));
                    *(float2*)(Out + obase + nt * 8) = o;
                } else {
                    float2 o; o.x = c0; o.y = c1;
                    *(float2*)(Out + obase + nt * 8) = o;
                }
            }
        }
    }
}

// ---------------- combine ----------------
__global__ void combine_kernel(const float* __restrict__ ew,
                               float* __restrict__ out) {
    int i = blockIdx.x * blockDim.x + threadIdx.x;
    const int n4 = TOKENS * HIDDEN / 4;
    if (i >= n4) return;
    int t  = i / (HIDDEN / 4);
    int c4 = (i % (HIDDEN / 4)) * 4;
    float w0 = ew[t * 2 + 0];
    float w1v = ew[t * 2 + 1];
    float4 y0 = *(const float4*)(g_y + (size_t)(2 * t + 0) * HIDDEN + c4);
    float4 y1 = *(const float4*)(g_y + (size_t)(2 * t + 1) * HIDDEN + c4);
    float4 o;
    o.x = w0 * y0.x + w1v * y1.x;
    o.y = w0 * y0.y + w1v * y1.y;
    o.z = w0 * y0.z + w1v * y1.z;
    o.w = w0 * y0.w + w1v * y1.w;
    *(float4*)(out + (size_t)t * HIDDEN + c4) = o;
}

// ---------------- launch ----------------
extern "C" void kernel_launch(void* const* d_in, const int* in_sizes, int n_in,
                              void* d_out, int out_size) {
    const float* x   = (const float*)d_in[0];
    const float* ew  = (const float*)d_in[1];
    const float* w1  = (const float*)d_in[2];
    const float* w2  = (const float*)d_in[3];
    const float* w3  = (const float*)d_in[4];
    const int*   idx = (const int*)d_in[5];
    float* out = (float*)d_out;

    float* gx = nullptr; float* gg = nullptr; float* gh = nullptr; float* gy = nullptr;
    cudaGetSymbolAddress((void**)&gx, g_x);
    cudaGetSymbolAddress((void**)&gg, g_gate);
    cudaGetSymbolAddress((void**)&gh, g_h);
    cudaGetSymbolAddress((void**)&gy, g_y);

    auto kGate = gemm_tc<HIDDEN, INTER, 1, 0>;
    auto kUp   = gemm_tc<HIDDEN, INTER, 1, 1>;
    auto kDown = gemm_tc<INTER, HIDDEN, 0, 0>;
    cudaFuncSetAttribute(kGate, cudaFuncAttributeMaxDynamicSharedMemorySize, G_SMEM);
    cudaFuncSetAttribute(kUp,   cudaFuncAttributeMaxDynamicSharedMemorySize, G_SMEM);
    cudaFuncSetAttribute(kDown, cudaFuncAttributeMaxDynamicSharedMemorySize, G_SMEM);

    zero_counts_kernel<<<1, 32>>>();
    route_kernel<<<NSLOTS / 256, 256>>>(idx);
    round_x_kernel<<<(TOKENS * HIDDEN / 4 + 255) / 256, 256>>>(x);

    dim3 g1(NSLOTS / 128, INTER / 128, NEXPERTS);   // Mtile fastest for L2 reuse
    kGate<<<g1, 128, G_SMEM>>>(gx, w1, nullptr, gg);
    kUp  <<<g1, 128, G_SMEM>>>(gx, w3, gg, gh);

    dim3 g2(NSLOTS / 128, HIDDEN / 128, NEXPERTS);
    kDown<<<g2, 128, G_SMEM>>>(gh, w2, nullptr, gy);

    combine_kernel<<<(TOKENS * HIDDEN / 4 + 255) / 256, 256>>>(ew, out);
}

// round 10
// speedup vs baseline: 1.1764x; 1.0951x over previous
#include <cuda_runtime.h>
#include <cuda_fp16.h>
#include <math.h>
#include <cstdint>

#define TOKENS  2048
#define HIDDEN  2048
#define INTER   5632
#define NEXPERTS 8
#define TOPK    2
#define NSLOTS  (TOKENS * TOPK)
#define BK 64

// ---------------- scratch ----------------
__device__ int    g_counts[NEXPERTS];
__device__ int    g_slots[NEXPERTS * NSLOTS];
__device__ __half g_xh[(size_t)TOKENS * HIDDEN];    // fp16-rounded x
__device__ float  g_gate[(size_t)NSLOTS * INTER];   // raw f32 gate
__device__ __half g_h[(size_t)NSLOTS * INTER];      // fp16 silu(g)*u
__device__ float  g_y[(size_t)NSLOTS * HIDDEN];

// ---------------- helpers ----------------
__device__ __forceinline__ uint32_t smem_u32(const void* p) {
    uint32_t a;
    asm("{ .reg .u64 t; cvta.to.shared.u64 t, %1; cvt.u32.u64 %0, t; }" : "=r"(a) : "l"(p));
    return a;
}
__device__ __forceinline__ void cp16(uint32_t dst, const void* src, int sz) {
    asm volatile("cp.async.cg.shared.global [%0], [%1], 16, %2;"
                 :: "r"(dst), "l"(src), "r"(sz) : "memory");
}
#define CP_COMMIT() asm volatile("cp.async.commit_group;" ::: "memory")
#define CP_WAIT0()  asm volatile("cp.async.wait_group 0;" ::: "memory")

__device__ __forceinline__ void ldsm4(uint32_t* r, uint32_t addr) {
    asm volatile("ldmatrix.sync.aligned.m8n8.x4.shared.b16 {%0,%1,%2,%3}, [%4];"
                 : "=r"(r[0]), "=r"(r[1]), "=r"(r[2]), "=r"(r[3]) : "r"(addr));
}
__device__ __forceinline__ void mma16(float* d, const uint32_t* a,
                                      uint32_t b0, uint32_t b1) {
    asm volatile(
        "mma.sync.aligned.m16n8k16.row.col.f32.f16.f16.f32 "
        "{%0,%1,%2,%3},{%4,%5,%6,%7},{%8,%9},{%0,%1,%2,%3};"
        : "+f"(d[0]), "+f"(d[1]), "+f"(d[2]), "+f"(d[3])
        : "r"(a[0]), "r"(a[1]), "r"(a[2]), "r"(a[3]), "r"(b0), "r"(b1));
}
__device__ __forceinline__ uint32_t pack2(float a, float b) {
    __half2 h = __floats2half2_rn(a, b);
    return *(uint32_t*)&h;
}
__device__ __forceinline__ float silu(float g) { return g / (1.f + expf(-g)); }

// ---------------- small kernels ----------------
__global__ void zero_counts_kernel() {
    if (threadIdx.x < NEXPERTS) g_counts[threadIdx.x] = 0;
}
__global__ void route_kernel(const int* __restrict__ idx) {
    int s = blockIdx.x * blockDim.x + threadIdx.x;
    if (s >= NSLOTS) return;
    int e = idx[s];
    int pos = atomicAdd(&g_counts[e], 1);
    g_slots[e * NSLOTS + pos] = s;
}
__global__ void round_x_kernel(const float* __restrict__ x) {
    int i = blockIdx.x * blockDim.x + threadIdx.x;
    if (i >= TOKENS * HIDDEN / 8) return;
    float4 v0 = *(const float4*)(x + i * 8);
    float4 v1 = *(const float4*)(x + i * 8 + 4);
    uint4 o;
    o.x = pack2(v0.x, v0.y);
    o.y = pack2(v0.z, v0.w);
    o.z = pack2(v1.x, v1.y);
    o.w = pack2(v1.z, v1.w);
    *(uint4*)(g_xh + (size_t)i * 8) = o;
}

// ================= unified grouped GEMM (fp16) =================
// CTA 128x128, BK=64. 4 warps (2x2), warp tile 64x64, 128 threads.
// smem (halves, 128B rows): A[2]@0 (16KB) | B[2]@32768 (16KB) | rows@65536
// EPI: 0 = raw f32 store; 1 = h = fp16(silu(gate)*acc)
#define G_SMEM 66048
extern __shared__ char smem[];

template<int KD, int ND, int SH, int EPI>
__global__ __launch_bounds__(128, 2)
void gemm_fp16(const __half* __restrict__ Abase,
               const float* __restrict__ Wbase,
               const float* __restrict__ Gate,
               float* __restrict__ OutF,
               __half* __restrict__ OutH) {
    const int e = blockIdx.z;
    const int count = g_counts[e];
    const int row0 = blockIdx.x * 128;
    if (row0 >= count) return;
    const int colbase = blockIdx.y * 128;

    const int tid  = threadIdx.x;
    const int lane = tid & 31;
    const int wid  = tid >> 5;
    const int q = lane & 3, gid = lane >> 2;
    const int warpm = wid >> 1;
    const int warpn = wid & 1;

    int* rowsS = (int*)(smem + 65536);
    if (tid < 128) {
        int r = row0 + tid;
        rowsS[tid] = (r < count) ? g_slots[e * NSLOTS + r] : -1;
    }
    __syncthreads();

    const uint32_t sb = smem_u32(smem);
    const float* Wp = Wbase + (size_t)e * KD * ND + colbase + tid;

    // ---- ldmatrix address precompute (XOR-folded, 128B rows of 64 halves) ----
    uint32_t BRA[4], MHA[4];
    {
        int cl = lane >> 4;                      // k-granule parity for A
        #pragma unroll
        for (int mt = 0; mt < 4; mt++) {
            int row = warpm * 64 + mt * 16 + ((lane >> 3) & 1) * 8 + (lane & 7);
            int m3 = row & 7;
            BRA[mt] = (uint32_t)(row * 128 + ((cl ^ (m3 & 1)) << 4));
            MHA[mt] = (uint32_t)(m3 >> 1);
        }
    }
    uint32_t BRB[4], MHB[4];
    {
        int cB = (lane >> 3) & 1;                // k-granule parity for B
        int jt = lane >> 4;                      // n-group offset
        #pragma unroll
        for (int u = 0; u < 4; u++) {
            int row = warpn * 64 + (2 * u + jt) * 8 + (lane & 7);
            int m3 = row & 7;
            BRB[u] = (uint32_t)(row * 128 + ((cB ^ (m3 & 1)) << 4));
            MHB[u] = (uint32_t)(m3 >> 1);
        }
    }

    // ---- A loader: 8 cp.async tasks; row = (tid>>3)+16p, granule ag = 8 halves ----
    const int ar0 = tid >> 3;
    const int ag  = tid & 7;
    const uint32_t dstA0 = (uint32_t)(ar0 * 128 + ((ag ^ (ar0 & 7)) << 4));
    int aslot[8];
    const __half* pAsrc[8];
    #pragma unroll
    for (int p = 0; p < 8; p++) {
        aslot[p] = rowsS[ar0 + p * 16];
        int arow = (aslot[p] >= 0) ? (aslot[p] >> SH) : 0;
        pAsrc[p] = Abase + (size_t)arow * KD + ag * 8;
    }
    // ---- B loader: n = tid, 8 granule-tasks of 8 k-halves ----
    const uint32_t stsB0 = (uint32_t)(tid * 128);
    const int bm3 = tid & 7;

    float acc[4][8][4];
    #pragma unroll
    for (int i = 0; i < 4; i++)
        #pragma unroll
        for (int j = 0; j < 8; j++)
            #pragma unroll
            for (int k = 0; k < 4; k++) acc[i][j][k] = 0.f;

    // ---- prologue: chunk 0 ----
    #pragma unroll
    for (int p = 0; p < 8; p++)
        cp16(sb + dstA0 + p * 2048, pAsrc[p], aslot[p] >= 0 ? 16 : 0);
    CP_COMMIT();
    #pragma unroll
    for (int p = 0; p < 8; p++) {
        float f[8];
        #pragma unroll
        for (int j = 0; j < 8; j++) f[j] = Wp[(size_t)(p * 8 + j) * ND];
        uint4 o;
        o.x = pack2(f[0], f[1]); o.y = pack2(f[2], f[3]);
        o.z = pack2(f[4], f[5]); o.w = pack2(f[6], f[7]);
        *(uint4*)(smem + 32768 + stsB0 + ((p ^ bm3) << 4)) = o;
    }
    CP_WAIT0();
    __syncthreads();

    float fb[32];
    const int NCH = KD / BK;
    for (int i = 0; i < NCH; i++) {
        const int cur = i & 1, nxt = cur ^ 1;
        const bool more = (i + 1 < NCH);
        const float* Wn = Wp + (size_t)(i + 1) * BK * ND;

        if (more) {
            #pragma unroll
            for (int p = 0; p < 8; p++)
                cp16(sb + nxt * 16384 + dstA0 + p * 2048,
                     pAsrc[p] + (size_t)(i + 1) * BK,
                     aslot[p] >= 0 ? 16 : 0);
            CP_COMMIT();
            // phase-0 B loads (granules 0..3)
            #pragma unroll
            for (int p = 0; p < 4; p++)
                #pragma unroll
                for (int j = 0; j < 8; j++)
                    fb[p * 8 + j] = Wn[(size_t)(p * 8 + j) * ND];
        }

        const uint32_t bufA = sb + cur * 16384;
        const uint32_t bufB = sb + 32768 + cur * 16384;

        // ---- mma ks = 0,1 ----
        #pragma unroll
        for (int ks = 0; ks < 2; ks++) {
            uint32_t a[4][4], b[4][4];
            #pragma unroll
            for (int mt = 0; mt < 4; mt++)
                ldsm4(a[mt], bufA + BRA[mt] + (((uint32_t)ks ^ MHA[mt]) << 5));
            #pragma unroll
            for (int u = 0; u < 4; u++)
                ldsm4(b[u], bufB + BRB[u] + (((uint32_t)ks ^ MHB[u]) << 5));
            #pragma unroll
            for (int mt = 0; mt < 4; mt++)
                #pragma unroll
                for (int nt = 0; nt < 8; nt++)
                    mma16(acc[mt][nt], a[mt],
                          b[nt >> 1][2 * (nt & 1)], b[nt >> 1][2 * (nt & 1) + 1]);
        }

        if (more) {
            // store phase-0, launch phase-1 loads (granules 4..7)
            #pragma unroll
            for (int p = 0; p < 4; p++) {
                uint4 o;
                o.x = pack2(fb[p * 8 + 0], fb[p * 8 + 1]);
                o.y = pack2(fb[p * 8 + 2], fb[p * 8 + 3]);
                o.z = pack2(fb[p * 8 + 4], fb[p * 8 + 5]);
                o.w = pack2(fb[p * 8 + 6], fb[p * 8 + 7]);
                *(uint4*)(smem + 32768 + nxt * 16384 + stsB0 + ((p ^ bm3) << 4)) = o;
            }
            #pragma unroll
            for (int p = 0; p < 4; p++)
                #pragma unroll
                for (int j = 0; j < 8; j++)
                    fb[p * 8 + j] = Wn[(size_t)((p + 4) * 8 + j) * ND];
        }

        // ---- mma ks = 2,3 ----
        #pragma unroll
        for (int ks = 2; ks < 4; ks++) {
            uint32_t a[4][4], b[4][4];
            #pragma unroll
            for (int mt = 0; mt < 4; mt++)
                ldsm4(a[mt], bufA + BRA[mt] + (((uint32_t)ks ^ MHA[mt]) << 5));
            #pragma unroll
            for (int u = 0; u < 4; u++)
                ldsm4(b[u], bufB + BRB[u] + (((uint32_t)ks ^ MHB[u]) << 5));
            #pragma unroll
            for (int mt = 0; mt < 4; mt++)
                #pragma unroll
                for (int nt = 0; nt < 8; nt++)
                    mma16(acc[mt][nt], a[mt],
                          b[nt >> 1][2 * (nt & 1)], b[nt >> 1][2 * (nt & 1) + 1]);
        }

        if (more) {
            #pragma unroll
            for (int p = 0; p < 4; p++) {
                uint4 o;
                o.x = pack2(fb[p * 8 + 0], fb[p * 8 + 1]);
                o.y = pack2(fb[p * 8 + 2], fb[p * 8 + 3]);
                o.z = pack2(fb[p * 8 + 4], fb[p * 8 + 5]);
                o.w = pack2(fb[p * 8 + 6], fb[p * 8 + 7]);
                *(uint4*)(smem + 32768 + nxt * 16384 + stsB0 + (((p + 4) ^ bm3) << 4)) = o;
            }
        }
        CP_WAIT0();
        __syncthreads();
    }

    // ---- epilogue ----
    #pragma unroll
    for (int mt = 0; mt < 4; mt++) {
        #pragma unroll
        for (int half = 0; half < 2; half++) {
            int row = warpm * 64 + mt * 16 + gid + half * 8;
            int slot = rowsS[row];
            if (slot < 0) continue;
            size_t obase = (size_t)slot * ND + colbase + warpn * 64 + 2 * q;
            #pragma unroll
            for (int nt = 0; nt < 8; nt++) {
                float c0 = acc[mt][nt][half * 2 + 0];
                float c1 = acc[mt][nt][half * 2 + 1];
                if (EPI == 1) {
                    float2 gv = *(const float2*)(Gate + obase + nt * 8);
                    uint32_t h2 = pack2(silu(gv.x) * c0, silu(gv.y) * c1);
                    *(uint32_t*)(OutH + obase + nt * 8) = h2;
                } else {
                    float2 o; o.x = c0; o.y = c1;
                    *(float2*)(OutF + obase + nt * 8) = o;
                }
            }
        }
    }
}

// ---------------- combine ----------------
__global__ void combine_kernel(const float* __restrict__ ew,
                               float* __restrict__ out) {
    int i = blockIdx.x * blockDim.x + threadIdx.x;
    const int n4 = TOKENS * HIDDEN / 4;
    if (i >= n4) return;
    int t  = i / (HIDDEN / 4);
    int c4 = (i % (HIDDEN / 4)) * 4;
    float w0 = ew[t * 2 + 0];
    float w1v = ew[t * 2 + 1];
    float4 y0 = *(const float4*)(g_y + (size_t)(2 * t + 0) * HIDDEN + c4);
    float4 y1 = *(const float4*)(g_y + (size_t)(2 * t + 1) * HIDDEN + c4);
    float4 o;
    o.x = w0 * y0.x + w1v * y1.x;
    o.y = w0 * y0.y + w1v * y1.y;
    o.z = w0 * y0.z + w1v * y1.z;
    o.w = w0 * y0.w + w1v * y1.w;
    *(float4*)(out + (size_t)t * HIDDEN + c4) = o;
}

// ---------------- launch ----------------
extern "C" void kernel_launch(void* const* d_in, const int* in_sizes, int n_in,
                              void* d_out, int out_size) {
    const float* x   = (const float*)d_in[0];
    const float* ew  = (const float*)d_in[1];
    const float* w1  = (const float*)d_in[2];
    const float* w2  = (const float*)d_in[3];
    const float* w3  = (const float*)d_in[4];
    const int*   idx = (const int*)d_in[5];
    float* out = (float*)d_out;

    __half* gxh = nullptr; float* gg = nullptr; __half* gh = nullptr; float* gy = nullptr;
    cudaGetSymbolAddress((void**)&gxh, g_xh);
    cudaGetSymbolAddress((void**)&gg, g_gate);
    cudaGetSymbolAddress((void**)&gh, g_h);
    cudaGetSymbolAddress((void**)&gy, g_y);

    auto kGate = gemm_fp16<HIDDEN, INTER, 1, 0>;
    auto kUp   = gemm_fp16<HIDDEN, INTER, 1, 1>;
    auto kDown = gemm_fp16<INTER, HIDDEN, 0, 0>;
    cudaFuncSetAttribute(kGate, cudaFuncAttributeMaxDynamicSharedMemorySize, G_SMEM);
    cudaFuncSetAttribute(kUp,   cudaFuncAttributeMaxDynamicSharedMemorySize, G_SMEM);
    cudaFuncSetAttribute(kDown, cudaFuncAttributeMaxDynamicSharedMemorySize, G_SMEM);

    zero_counts_kernel<<<1, 32>>>();
    route_kernel<<<NSLOTS / 256, 256>>>(idx);
    round_x_kernel<<<(TOKENS * HIDDEN / 8 + 255) / 256, 256>>>(x);

    dim3 g1(NSLOTS / 128, INTER / 128, NEXPERTS);   // Mtile fastest for L2 reuse
    kGate<<<g1, 128, G_SMEM>>>(gxh, w1, nullptr, gg, nullptr);
    kUp  <<<g1, 128, G_SMEM>>>(gxh, w3, gg, nullptr, gh);

    dim3 g2(NSLOTS / 128, HIDDEN / 128, NEXPERTS);
    kDown<<<g2, 128, G_SMEM>>>(gh, w2, nullptr, gy, nullptr);

    combine_kernel<<<(TOKENS * HIDDEN / 4 + 255) / 256, 256>>>(ew, out);
}

// round 11
// speedup vs baseline: 1.6873x; 1.4342x over previous
#include <cuda_runtime.h>
#include <cuda_fp16.h>
#include <math.h>
#include <cstdint>

#define TOKENS  2048
#define HIDDEN  2048
#define INTER   5632
#define NEXPERTS 8
#define TOPK    2
#define NSLOTS  (TOKENS * TOPK)
#define BK 64

// ---------------- scratch ----------------
__device__ int    g_counts[NEXPERTS];
__device__ int    g_slots[NEXPERTS * NSLOTS];
__device__ __half g_xh[(size_t)TOKENS * HIDDEN];    // fp16-rounded x
__device__ float  g_gate[(size_t)NSLOTS * INTER];   // raw f32 gate
__device__ __half g_h[(size_t)NSLOTS * INTER];      // fp16 silu(g)*u
__device__ float  g_y[(size_t)NSLOTS * HIDDEN];

// ---------------- helpers ----------------
__device__ __forceinline__ uint32_t smem_u32(const void* p) {
    uint32_t a;
    asm("{ .reg .u64 t; cvta.to.shared.u64 t, %1; cvt.u32.u64 %0, t; }" : "=r"(a) : "l"(p));
    return a;
}
__device__ __forceinline__ void cp16(uint32_t dst, const void* src, int sz) {
    asm volatile("cp.async.cg.shared.global [%0], [%1], 16, %2;"
                 :: "r"(dst), "l"(src), "r"(sz) : "memory");
}
#define CP_COMMIT() asm volatile("cp.async.commit_group;" ::: "memory")
#define CP_WAIT0()  asm volatile("cp.async.wait_group 0;" ::: "memory")

__device__ __forceinline__ void ldsm4(uint32_t* r, uint32_t addr) {
    asm volatile("ldmatrix.sync.aligned.m8n8.x4.shared.b16 {%0,%1,%2,%3}, [%4];"
                 : "=r"(r[0]), "=r"(r[1]), "=r"(r[2]), "=r"(r[3]) : "r"(addr));
}
__device__ __forceinline__ void mma16(float* d, const uint32_t* a,
                                      uint32_t b0, uint32_t b1) {
    asm volatile(
        "mma.sync.aligned.m16n8k16.row.col.f32.f16.f16.f32 "
        "{%0,%1,%2,%3},{%4,%5,%6,%7},{%8,%9},{%0,%1,%2,%3};"
        : "+f"(d[0]), "+f"(d[1]), "+f"(d[2]), "+f"(d[3])
        : "r"(a[0]), "r"(a[1]), "r"(a[2]), "r"(a[3]), "r"(b0), "r"(b1));
}
__device__ __forceinline__ uint32_t pack2(float a, float b) {
    __half2 h = __floats2half2_rn(a, b);
    return *(uint32_t*)&h;
}
__device__ __forceinline__ float silu(float g) { return g / (1.f + expf(-g)); }

// ---------------- small kernels ----------------
__global__ void zero_counts_kernel() {
    if (threadIdx.x < NEXPERTS) g_counts[threadIdx.x] = 0;
}
__global__ void route_kernel(const int* __restrict__ idx) {
    int s = blockIdx.x * blockDim.x + threadIdx.x;
    if (s >= NSLOTS) return;
    int e = idx[s];
    int pos = atomicAdd(&g_counts[e], 1);
    g_slots[e * NSLOTS + pos] = s;
}
__global__ void round_x_kernel(const float* __restrict__ x) {
    int i = blockIdx.x * blockDim.x + threadIdx.x;
    if (i >= TOKENS * HIDDEN / 8) return;
    float4 v0 = *(const float4*)(x + i * 8);
    float4 v1 = *(const float4*)(x + i * 8 + 4);
    uint4 o;
    o.x = pack2(v0.x, v0.y);
    o.y = pack2(v0.z, v0.w);
    o.z = pack2(v1.x, v1.y);
    o.w = pack2(v1.z, v1.w);
    *(uint4*)(g_xh + (size_t)i * 8) = o;
}

// ================= unified grouped GEMM (fp16) =================
// CTA 128x128, BK=64. 4 warps (2x2), warp tile 64x64, 128 threads.
// smem (halves, 128B rows): A[2]@0 (16KB) | B[2]@32768 (16KB) | rows@65536
// EPI: 0 = raw f32 store; 1 = h = fp16(silu(gate)*acc)
#define G_SMEM 66048
extern __shared__ char smem[];

template<int KD, int ND, int SH, int EPI>
__global__ __launch_bounds__(128, 2)
void gemm_fp16(const __half* __restrict__ Abase,
               const float* __restrict__ Wbase,
               const float* __restrict__ Gate,
               float* __restrict__ OutF,
               __half* __restrict__ OutH) {
    const int e = blockIdx.z;
    const int count = g_counts[e];
    const int row0 = blockIdx.x * 128;
    if (row0 >= count) return;
    const int colbase = blockIdx.y * 128;

    const int tid  = threadIdx.x;
    const int lane = tid & 31;
    const int wid  = tid >> 5;
    const int q = lane & 3, gid = lane >> 2;
    const int warpm = wid >> 1;
    const int warpn = wid & 1;

    int* rowsS = (int*)(smem + 65536);
    if (tid < 128) {
        int r = row0 + tid;
        rowsS[tid] = (r < count) ? g_slots[e * NSLOTS + r] : -1;
    }
    __syncthreads();

    const uint32_t sb = smem_u32(smem);
    const float* Wp = Wbase + (size_t)e * KD * ND + colbase + tid;

    // ---- ldmatrix address precompute (XOR-folded, 128B rows of 64 halves) ----
    uint32_t BRA[4], MHA[4];
    {
        int cl = lane >> 4;
        #pragma unroll
        for (int mt = 0; mt < 4; mt++) {
            int row = warpm * 64 + mt * 16 + ((lane >> 3) & 1) * 8 + (lane & 7);
            int m3 = row & 7;
            BRA[mt] = (uint32_t)(row * 128 + ((cl ^ (m3 & 1)) << 4));
            MHA[mt] = (uint32_t)(m3 >> 1);
        }
    }
    uint32_t BRB[4], MHB[4];
    {
        int cB = (lane >> 3) & 1;
        int jt = lane >> 4;
        #pragma unroll
        for (int u = 0; u < 4; u++) {
            int row = warpn * 64 + (2 * u + jt) * 8 + (lane & 7);
            int m3 = row & 7;
            BRB[u] = (uint32_t)(row * 128 + ((cB ^ (m3 & 1)) << 4));
            MHB[u] = (uint32_t)(m3 >> 1);
        }
    }

    // ---- A loader tasks ----
    const int ar0 = tid >> 3;
    const int ag  = tid & 7;
    const uint32_t dstA0 = (uint32_t)(ar0 * 128 + ((ag ^ (ar0 & 7)) << 4));
    int aslot[8];
    const __half* pAsrc[8];
    #pragma unroll
    for (int p = 0; p < 8; p++) {
        aslot[p] = rowsS[ar0 + p * 16];
        int arow = (aslot[p] >= 0) ? (aslot[p] >> SH) : 0;
        pAsrc[p] = Abase + (size_t)arow * KD + ag * 8;
    }
    // ---- B loader: n = tid, 8 granule-tasks of 8 k-halves ----
    const uint32_t stsB0 = (uint32_t)(tid * 128);
    const int bm3 = tid & 7;

    float acc[4][8][4];
    #pragma unroll
    for (int i = 0; i < 4; i++)
        #pragma unroll
        for (int j = 0; j < 8; j++)
            #pragma unroll
            for (int k = 0; k < 4; k++) acc[i][j][k] = 0.f;

    // ---- prologue: chunk 0 ----
    #pragma unroll
    for (int p = 0; p < 8; p++)
        cp16(sb + dstA0 + p * 2048, pAsrc[p], aslot[p] >= 0 ? 16 : 0);
    CP_COMMIT();
    #pragma unroll
    for (int p = 0; p < 8; p++) {
        float f[8];
        #pragma unroll
        for (int j = 0; j < 8; j++) f[j] = Wp[(size_t)(p * 8 + j) * ND];
        uint4 o;
        o.x = pack2(f[0], f[1]); o.y = pack2(f[2], f[3]);
        o.z = pack2(f[4], f[5]); o.w = pack2(f[6], f[7]);
        *(uint4*)(smem + 32768 + stsB0 + ((p ^ bm3) << 4)) = o;
    }
    CP_WAIT0();
    __syncthreads();

    float fb[32];
    const int NCH = KD / BK;
    for (int i = 0; i < NCH; i++) {
        const int cur = i & 1, nxt = cur ^ 1;
        const bool more = (i + 1 < NCH);
        const float* Wn = Wp + (size_t)(i + 1) * BK * ND;

        if (more) {
            // async A prefetch for next chunk
            #pragma unroll
            for (int p = 0; p < 8; p++)
                cp16(sb + nxt * 16384 + dstA0 + p * 2048,
                     pAsrc[p] + (size_t)(i + 1) * BK,
                     aslot[p] >= 0 ? 16 : 0);
            CP_COMMIT();
            // ALL B LDGs for next chunk issued here — full 64-HMMA burst of latency cover
            #pragma unroll
            for (int p = 0; p < 8; p++)
                #pragma unroll
                for (int j = 0; j < 4; j++)
                    fb[p * 4 + j] = Wn[(size_t)(p * 8 + 2 * j) * ND];
            // second element of each pair loaded into the other half below
        }

        const uint32_t bufA = sb + cur * 16384;
        const uint32_t bufB = sb + 32768 + cur * 16384;

        // ---- mma ks = 0,1 ----
        #pragma unroll
        for (int ks = 0; ks < 2; ks++) {
            uint32_t a[4][4], b[4][4];
            #pragma unroll
            for (int mt = 0; mt < 4; mt++)
                ldsm4(a[mt], bufA + BRA[mt] + (((uint32_t)ks ^ MHA[mt]) << 5));
            #pragma unroll
            for (int u = 0; u < 4; u++)
                ldsm4(b[u], bufB + BRB[u] + (((uint32_t)ks ^ MHB[u]) << 5));
            #pragma unroll
            for (int mt = 0; mt < 4; mt++)
                #pragma unroll
                for (int nt = 0; nt < 8; nt++)
                    mma16(acc[mt][nt], a[mt],
                          b[nt >> 1][2 * (nt & 1)], b[nt >> 1][2 * (nt & 1) + 1]);
        }

        float fb2[32];
        if (more) {
            // odd-index B elements; still ~32 HMMA of cover before use
            #pragma unroll
            for (int p = 0; p < 8; p++)
                #pragma unroll
                for (int j = 0; j < 4; j++)
                    fb2[p * 4 + j] = Wn[(size_t)(p * 8 + 2 * j + 1) * ND];
        }

        // ---- mma ks = 2,3 ----
        #pragma unroll
        for (int ks = 2; ks < 4; ks++) {
            uint32_t a[4][4], b[4][4];
            #pragma unroll
            for (int mt = 0; mt < 4; mt++)
                ldsm4(a[mt], bufA + BRA[mt] + (((uint32_t)ks ^ MHA[mt]) << 5));
            #pragma unroll
            for (int u = 0; u < 4; u++)
                ldsm4(b[u], bufB + BRB[u] + (((uint32_t)ks ^ MHB[u]) << 5));
            #pragma unroll
            for (int mt = 0; mt < 4; mt++)
                #pragma unroll
                for (int nt = 0; nt < 8; nt++)
                    mma16(acc[mt][nt], a[mt],
                          b[nt >> 1][2 * (nt & 1)], b[nt >> 1][2 * (nt & 1) + 1]);
        }

        if (more) {
            // single STS phase at chunk end: all LDGs have had a full burst to land
            #pragma unroll
            for (int p = 0; p < 8; p++) {
                uint4 o;
                o.x = pack2(fb[p * 4 + 0], fb2[p * 4 + 0]);
                o.y = pack2(fb[p * 4 + 1], fb2[p * 4 + 1]);
                o.z = pack2(fb[p * 4 + 2], fb2[p * 4 + 2]);
                o.w = pack2(fb[p * 4 + 3], fb2[p * 4 + 3]);
                *(uint4*)(smem + 32768 + nxt * 16384 + stsB0 + ((p ^ bm3) << 4)) = o;
            }
        }
        CP_WAIT0();
        __syncthreads();
    }

    // ---- epilogue ----
    #pragma unroll
    for (int mt = 0; mt < 4; mt++) {
        #pragma unroll
        for (int half = 0; half < 2; half++) {
            int row = warpm * 64 + mt * 16 + gid + half * 8;
            int slot = rowsS[row];
            if (slot < 0) continue;
            size_t obase = (size_t)slot * ND + colbase + warpn * 64 + 2 * q;
            #pragma unroll
            for (int nt = 0; nt < 8; nt++) {
                float c0 = acc[mt][nt][half * 2 + 0];
                float c1 = acc[mt][nt][half * 2 + 1];
                if (EPI == 1) {
                    float2 gv = *(const float2*)(Gate + obase + nt * 8);
                    uint32_t h2 = pack2(silu(gv.x) * c0, silu(gv.y) * c1);
                    *(uint32_t*)(OutH + obase + nt * 8) = h2;
                } else {
                    float2 o; o.x = c0; o.y = c1;
                    *(float2*)(OutF + obase + nt * 8) = o;
                }
            }
        }
    }
}

// ---------------- combine ----------------
__global__ void combine_kernel(const float* __restrict__ ew,
                               float* __restrict__ out) {
    int i = blockIdx.x * blockDim.x + threadIdx.x;
    const int n4 = TOKENS * HIDDEN / 4;
    if (i >= n4) return;
    int t  = i / (HIDDEN / 4);
    int c4 = (i % (HIDDEN / 4)) * 4;
    float w0 = ew[t * 2 + 0];
    float w1v = ew[t * 2 + 1];
    float4 y0 = *(const float4*)(g_y + (size_t)(2 * t + 0) * HIDDEN + c4);
    float4 y1 = *(const float4*)(g_y + (size_t)(2 * t + 1) * HIDDEN + c4);
    float4 o;
    o.x = w0 * y0.x + w1v * y1.x;
    o.y = w0 * y0.y + w1v * y1.y;
    o.z = w0 * y0.z + w1v * y1.z;
    o.w = w0 * y0.w + w1v * y1.w;
    *(float4*)(out + (size_t)t * HIDDEN + c4) = o;
}

// ---------------- launch ----------------
extern "C" void kernel_launch(void* const* d_in, const int* in_sizes, int n_in,
                              void* d_out, int out_size) {
    const float* x   = (const float*)d_in[0];
    const float* ew  = (const float*)d_in[1];
    const float* w1  = (const float*)d_in[2];
    const float* w2  = (const float*)d_in[3];
    const float* w3  = (const float*)d_in[4];
    const int*   idx = (const int*)d_in[5];
    float* out = (float*)d_out;

    __half* gxh = nullptr; float* gg = nullptr; __half* gh = nullptr; float* gy = nullptr;
    cudaGetSymbolAddress((void**)&gxh, g_xh);
    cudaGetSymbolAddress((void**)&gg, g_gate);
    cudaGetSymbolAddress((void**)&gh, g_h);
    cudaGetSymbolAddress((void**)&gy, g_y);

    auto kGate = gemm_fp16<HIDDEN, INTER, 1, 0>;
    auto kUp   = gemm_fp16<HIDDEN, INTER, 1, 1>;
    auto kDown = gemm_fp16<INTER, HIDDEN, 0, 0>;
    cudaFuncSetAttribute(kGate, cudaFuncAttributeMaxDynamicSharedMemorySize, G_SMEM);
    cudaFuncSetAttribute(kUp,   cudaFuncAttributeMaxDynamicSharedMemorySize, G_SMEM);
    cudaFuncSetAttribute(kDown, cudaFuncAttributeMaxDynamicSharedMemorySize, G_SMEM);

    zero_counts_kernel<<<1, 32>>>();
    route_kernel<<<NSLOTS / 256, 256>>>(idx);
    round_x_kernel<<<(TOKENS * HIDDEN / 8 + 255) / 256, 256>>>(x);

    dim3 g1(NSLOTS / 128, INTER / 128, NEXPERTS);   // Mtile fastest for L2 reuse
    kGate<<<g1, 128, G_SMEM>>>(gxh, w1, nullptr, gg, nullptr);
    kUp  <<<g1, 128, G_SMEM>>>(gxh, w3, gg, nullptr, gh);

    dim3 g2(NSLOTS / 128, HIDDEN / 128, NEXPERTS);
    kDown<<<g2, 128, G_SMEM>>>(gh, w2, nullptr, gy, nullptr);

    combine_kernel<<<(TOKENS * HIDDEN / 4 + 255) / 256, 256>>>(ew, out);
}